// round 1
// baseline (speedup 1.0000x reference)
#include <cuda_runtime.h>
#include <math.h>

#define Bb 16
#define Cc 512
#define Ll 1024
#define C3 1536
#define BN_EPS 1e-5f

// ---- scratch (no allocations allowed) ----
__device__ float g_scale[Cc];
__device__ float g_shift[Cc];
__device__ float g_Wall[C3 * Cc];          // folded stacked QKV weights [1536][512]
__device__ float g_ball[C3];               // folded stacked biases
__device__ float g_qkv[(size_t)Bb * C3 * Ll];   // [B][1536][L]  (q rows 0..511, k 512..1023, v 1024..1535)
__device__ float g_S[(size_t)Bb * Ll * Ll];     // attention scores/probs [B][L][L]
__device__ float g_h[(size_t)Bb * Cc * Ll];     // attn @ V^T result [B][C][L]

// ============================================================
// 1) BatchNorm batch statistics -> per-channel scale/shift
// ============================================================
__global__ __launch_bounds__(256) void bn_stats_kernel(
    const float* __restrict__ x, const float* __restrict__ gamma,
    const float* __restrict__ beta)
{
    int c = blockIdx.x;
    int tid = threadIdx.x;
    const float* xp = x + (size_t)c * Ll;
    float s = 0.f, s2 = 0.f;
    for (int i = tid; i < Bb * Ll; i += 256) {
        int b = i >> 10, l = i & (Ll - 1);
        float v = xp[(size_t)b * Cc * Ll + l];
        s += v; s2 += v * v;
    }
    __shared__ float sh1[256], sh2[256];
    sh1[tid] = s; sh2[tid] = s2; __syncthreads();
    for (int o = 128; o > 0; o >>= 1) {
        if (tid < o) { sh1[tid] += sh1[tid + o]; sh2[tid] += sh2[tid + o]; }
        __syncthreads();
    }
    if (tid == 0) {
        const float inv_n = 1.f / (float)(Bb * Ll);
        float mean = sh1[0] * inv_n;
        float var = sh2[0] * inv_n - mean * mean;
        float sc = gamma[c] * rsqrtf(var + BN_EPS);
        g_scale[c] = sc;
        g_shift[c] = beta[c] - mean * sc;
    }
}

// ============================================================
// 2) Fold BN affine into stacked QKV weights/biases
// ============================================================
__global__ __launch_bounds__(256) void fold_kernel(
    const float* __restrict__ Wq, const float* __restrict__ bq,
    const float* __restrict__ Wk, const float* __restrict__ bk,
    const float* __restrict__ Wv, const float* __restrict__ bv)
{
    int o = blockIdx.x;           // 0..1535
    int r = o & (Cc - 1);
    const float* W; const float* bb;
    if (o < Cc)          { W = Wq; bb = bq; }
    else if (o < 2 * Cc) { W = Wk; bb = bk; }
    else                 { W = Wv; bb = bv; }
    int tid = threadIdx.x;
    float acc = 0.f;
    for (int c = tid; c < Cc; c += 256) {
        float w = W[r * Cc + c];
        g_Wall[o * Cc + c] = w * g_scale[c];
        acc += w * g_shift[c];
    }
    __shared__ float sh[256];
    sh[tid] = acc; __syncthreads();
    for (int off = 128; off > 0; off >>= 1) {
        if (tid < off) sh[tid] += sh[tid + off];
        __syncthreads();
    }
    if (tid == 0) g_ball[o] = bb[r] + sh[0];
}

// ============================================================
// 3) QKV GEMM:  qkv[b][o][l] = sum_c Wall[o][c] * x[b][c][l] + ball[o]
//    A row-major k-contig, B row-major n-contig. 64x64x16 tiles.
// ============================================================
__global__ __launch_bounds__(256) void gemm_qkv_kernel(const float* __restrict__ x)
{
    int b = blockIdx.z;
    int m0 = blockIdx.y * 64;
    int n0 = blockIdx.x * 64;
    const float* Bp = x + (size_t)b * Cc * Ll;

    __shared__ float As[64][17];   // A[m][k]
    __shared__ float Bs[16][64];   // B[k][n]

    int tid = threadIdx.x;
    int tx = tid & 15, ty = tid >> 4;
    int arow = tid >> 2, acol = (tid & 3) * 4;    // A loader: 64 rows x 16 k
    int brow = tid >> 4, bcol = (tid & 15) * 4;   // B loader: 16 k x 64 n

    float acc[4][4] = {};
    for (int k0 = 0; k0 < Cc; k0 += 16) {
        float4 av = *(const float4*)&g_Wall[(m0 + arow) * Cc + k0 + acol];
        As[arow][acol + 0] = av.x; As[arow][acol + 1] = av.y;
        As[arow][acol + 2] = av.z; As[arow][acol + 3] = av.w;
        *(float4*)&Bs[brow][bcol] =
            *(const float4*)&Bp[(size_t)(k0 + brow) * Ll + n0 + bcol];
        __syncthreads();
#pragma unroll
        for (int k = 0; k < 16; k++) {
            float a[4], bv[4];
#pragma unroll
            for (int i = 0; i < 4; i++) a[i] = As[ty * 4 + i][k];
#pragma unroll
            for (int j = 0; j < 4; j++) bv[j] = Bs[k][tx * 4 + j];
#pragma unroll
            for (int i = 0; i < 4; i++)
#pragma unroll
                for (int j = 0; j < 4; j++) acc[i][j] += a[i] * bv[j];
        }
        __syncthreads();
    }
    float* Cp = g_qkv + (size_t)b * C3 * Ll;
#pragma unroll
    for (int i = 0; i < 4; i++) {
        int m = m0 + ty * 4 + i;
        float bias = g_ball[m];
        float4 r;
        r.x = acc[i][0] + bias; r.y = acc[i][1] + bias;
        r.z = acc[i][2] + bias; r.w = acc[i][3] + bias;
        *(float4*)&Cp[(size_t)m * Ll + n0 + tx * 4] = r;
    }
}

// ============================================================
// 4) Scores GEMM: S[b][i][j] = (1/sqrt(C)) * sum_c q[b][c][i] * k[b][c][j]
//    Both operands are [K=C][M/N=L] (k is the slow dim) -> direct [k][m] loads.
// ============================================================
__global__ __launch_bounds__(256) void gemm_scores_kernel()
{
    int b = blockIdx.z;
    int m0 = blockIdx.y * 64;   // i
    int n0 = blockIdx.x * 64;   // j
    const float* Qp = g_qkv + (size_t)b * C3 * Ll;       // [C][L]
    const float* Kp = Qp + (size_t)Cc * Ll;

    __shared__ float As[16][64];
    __shared__ float Bs[16][64];

    int tid = threadIdx.x;
    int tx = tid & 15, ty = tid >> 4;
    int lrow = tid >> 4, lcol = (tid & 15) * 4;   // 16 k x 64 m/n

    float acc[4][4] = {};
    for (int k0 = 0; k0 < Cc; k0 += 16) {
        *(float4*)&As[lrow][lcol] =
            *(const float4*)&Qp[(size_t)(k0 + lrow) * Ll + m0 + lcol];
        *(float4*)&Bs[lrow][lcol] =
            *(const float4*)&Kp[(size_t)(k0 + lrow) * Ll + n0 + lcol];
        __syncthreads();
#pragma unroll
        for (int k = 0; k < 16; k++) {
            float a[4], bv[4];
#pragma unroll
            for (int i = 0; i < 4; i++) a[i] = As[k][ty * 4 + i];
#pragma unroll
            for (int j = 0; j < 4; j++) bv[j] = Bs[k][tx * 4 + j];
#pragma unroll
            for (int i = 0; i < 4; i++)
#pragma unroll
                for (int j = 0; j < 4; j++) acc[i][j] += a[i] * bv[j];
        }
        __syncthreads();
    }
    const float invs = rsqrtf((float)Cc);
    float* Sp = g_S + (size_t)b * Ll * Ll;
#pragma unroll
    for (int i = 0; i < 4; i++) {
        int m = m0 + ty * 4 + i;
        float4 r;
        r.x = acc[i][0] * invs; r.y = acc[i][1] * invs;
        r.z = acc[i][2] * invs; r.w = acc[i][3] * invs;
        *(float4*)&Sp[(size_t)m * Ll + n0 + tx * 4] = r;
    }
}

// ============================================================
// 5) Row softmax over the last dim of S (in place). One block per row.
// ============================================================
__global__ __launch_bounds__(256) void softmax_kernel()
{
    size_t row = blockIdx.x;   // b*L + i
    float* Sp = g_S + row * (size_t)Ll;
    int tid = threadIdx.x;
    float4 v = ((float4*)Sp)[tid];

    __shared__ float sh[256];
    float mx = fmaxf(fmaxf(v.x, v.y), fmaxf(v.z, v.w));
    sh[tid] = mx; __syncthreads();
    for (int o = 128; o > 0; o >>= 1) {
        if (tid < o) sh[tid] = fmaxf(sh[tid], sh[tid + o]);
        __syncthreads();
    }
    float rowmax = sh[0];
    __syncthreads();

    v.x = __expf(v.x - rowmax); v.y = __expf(v.y - rowmax);
    v.z = __expf(v.z - rowmax); v.w = __expf(v.w - rowmax);
    sh[tid] = v.x + v.y + v.z + v.w; __syncthreads();
    for (int o = 128; o > 0; o >>= 1) {
        if (tid < o) sh[tid] += sh[tid + o];
        __syncthreads();
    }
    float inv = 1.f / sh[0];
    v.x *= inv; v.y *= inv; v.z *= inv; v.w *= inv;
    ((float4*)Sp)[tid] = v;
}

// ============================================================
// 6) attn @ V^T:  h[b][c][i] = sum_j P[b][i][j] * v[b][c][j]
//    A = V [m=c][k=j] k-contig, B = P [n=i][k=j] k-contig.
// ============================================================
__global__ __launch_bounds__(256) void gemm_av_kernel()
{
    int b = blockIdx.z;
    int m0 = blockIdx.y * 64;   // c
    int n0 = blockIdx.x * 64;   // i
    const float* Vp = g_qkv + (size_t)b * C3 * Ll + (size_t)2 * Cc * Ll;  // [C][L]
    const float* Pp = g_S + (size_t)b * Ll * Ll;                          // [L][L]

    __shared__ float As[64][17];
    __shared__ float Bs[64][17];

    int tid = threadIdx.x;
    int tx = tid & 15, ty = tid >> 4;
    int lrow = tid >> 2, lcol = (tid & 3) * 4;   // 64 rows x 16 k

    float acc[4][4] = {};
    for (int k0 = 0; k0 < Ll; k0 += 16) {
        float4 av = *(const float4*)&Vp[(size_t)(m0 + lrow) * Ll + k0 + lcol];
        As[lrow][lcol + 0] = av.x; As[lrow][lcol + 1] = av.y;
        As[lrow][lcol + 2] = av.z; As[lrow][lcol + 3] = av.w;
        float4 bv4 = *(const float4*)&Pp[(size_t)(n0 + lrow) * Ll + k0 + lcol];
        Bs[lrow][lcol + 0] = bv4.x; Bs[lrow][lcol + 1] = bv4.y;
        Bs[lrow][lcol + 2] = bv4.z; Bs[lrow][lcol + 3] = bv4.w;
        __syncthreads();
#pragma unroll
        for (int k = 0; k < 16; k++) {
            float a[4], bv[4];
#pragma unroll
            for (int i = 0; i < 4; i++) a[i] = As[ty * 4 + i][k];
#pragma unroll
            for (int j = 0; j < 4; j++) bv[j] = Bs[tx * 4 + j][k];
#pragma unroll
            for (int i = 0; i < 4; i++)
#pragma unroll
                for (int j = 0; j < 4; j++) acc[i][j] += a[i] * bv[j];
        }
        __syncthreads();
    }
    float* Hp = g_h + (size_t)b * Cc * Ll;
#pragma unroll
    for (int i = 0; i < 4; i++) {
        int m = m0 + ty * 4 + i;
        float4 r;
        r.x = acc[i][0]; r.y = acc[i][1]; r.z = acc[i][2]; r.w = acc[i][3];
        *(float4*)&Hp[(size_t)m * Ll + n0 + tx * 4] = r;
    }
}

// ============================================================
// 7) Projection + residual: out[b][o][l] = x[b][o][l] + bp[o] + sum_c Wp[o][c]*h[b][c][l]
// ============================================================
__global__ __launch_bounds__(256) void gemm_proj_kernel(
    const float* __restrict__ x, const float* __restrict__ Wp,
    const float* __restrict__ bp, float* __restrict__ out)
{
    int b = blockIdx.z;
    int m0 = blockIdx.y * 64;
    int n0 = blockIdx.x * 64;
    const float* Bp = g_h + (size_t)b * Cc * Ll;

    __shared__ float As[64][17];
    __shared__ float Bs[16][64];

    int tid = threadIdx.x;
    int tx = tid & 15, ty = tid >> 4;
    int arow = tid >> 2, acol = (tid & 3) * 4;
    int brow = tid >> 4, bcol = (tid & 15) * 4;

    float acc[4][4] = {};
    for (int k0 = 0; k0 < Cc; k0 += 16) {
        float4 av = *(const float4*)&Wp[(m0 + arow) * Cc + k0 + acol];
        As[arow][acol + 0] = av.x; As[arow][acol + 1] = av.y;
        As[arow][acol + 2] = av.z; As[arow][acol + 3] = av.w;
        *(float4*)&Bs[brow][bcol] =
            *(const float4*)&Bp[(size_t)(k0 + brow) * Ll + n0 + bcol];
        __syncthreads();
#pragma unroll
        for (int k = 0; k < 16; k++) {
            float a[4], bv[4];
#pragma unroll
            for (int i = 0; i < 4; i++) a[i] = As[ty * 4 + i][k];
#pragma unroll
            for (int j = 0; j < 4; j++) bv[j] = Bs[k][tx * 4 + j];
#pragma unroll
            for (int i = 0; i < 4; i++)
#pragma unroll
                for (int j = 0; j < 4; j++) acc[i][j] += a[i] * bv[j];
        }
        __syncthreads();
    }
#pragma unroll
    for (int i = 0; i < 4; i++) {
        int m = m0 + ty * 4 + i;
        size_t off = (size_t)b * Cc * Ll + (size_t)m * Ll + n0 + tx * 4;
        float bias = bp[m];
        float4 xr = *(const float4*)&x[off];
        float4 r;
        r.x = acc[i][0] + bias + xr.x;
        r.y = acc[i][1] + bias + xr.y;
        r.z = acc[i][2] + bias + xr.z;
        r.w = acc[i][3] + bias + xr.w;
        *(float4*)&out[off] = r;
    }
}

// ============================================================
extern "C" void kernel_launch(void* const* d_in, const int* in_sizes, int n_in,
                              void* d_out, int out_size)
{
    const float* x     = (const float*)d_in[0];
    const float* gamma = (const float*)d_in[1];
    const float* beta  = (const float*)d_in[2];
    const float* Wq    = (const float*)d_in[3];
    const float* bq    = (const float*)d_in[4];
    const float* Wk    = (const float*)d_in[5];
    const float* bk    = (const float*)d_in[6];
    const float* Wv    = (const float*)d_in[7];
    const float* bv    = (const float*)d_in[8];
    const float* Wp    = (const float*)d_in[9];
    const float* bp    = (const float*)d_in[10];
    float* out = (float*)d_out;

    bn_stats_kernel<<<Cc, 256>>>(x, gamma, beta);
    fold_kernel<<<C3, 256>>>(Wq, bq, Wk, bk, Wv, bv);
    gemm_qkv_kernel<<<dim3(Ll / 64, C3 / 64, Bb), 256>>>(x);
    gemm_scores_kernel<<<dim3(Ll / 64, Ll / 64, Bb), 256>>>();
    softmax_kernel<<<Bb * Ll, 256>>>();
    gemm_av_kernel<<<dim3(Ll / 64, Cc / 64, Bb), 256>>>();
    gemm_proj_kernel<<<dim3(Ll / 64, Cc / 64, Bb), 256>>>(x, Wp, bp, out);
}

// round 2
// speedup vs baseline: 2.4719x; 2.4719x over previous
#include <cuda_runtime.h>
#include <math.h>
#include <stdint.h>

#define Bb 16
#define Cc 512
#define Ll 1024
#define C3 1536
#define BN_EPS 1e-5f

// ---- scratch (no allocations allowed) ----
__device__ float g_scale[Cc];
__device__ float g_shift[Cc];
__device__ float g_Wall[C3 * Cc];               // folded stacked QKV weights [1536][512]
__device__ float g_ball[C3];                    // folded stacked biases
__device__ float g_qkv[(size_t)Bb * C3 * Ll];   // [B][1536][L]
__device__ float g_S[(size_t)Bb * Ll * Ll];     // attention scores/probs [B][L][L]
__device__ float g_h[(size_t)Bb * Cc * Ll];     // attn @ V^T result [B][C][L]

__device__ __forceinline__ float to_tf32(float x) {
    float y;
    asm("cvt.rna.tf32.f32 %0, %1;" : "=f"(y) : "f"(x));
    return y;
}

// ============================================================
// 1) BatchNorm batch statistics -> per-channel scale/shift
// ============================================================
__global__ __launch_bounds__(256) void bn_stats_kernel(
    const float* __restrict__ x, const float* __restrict__ gamma,
    const float* __restrict__ beta)
{
    int c = blockIdx.x;
    int tid = threadIdx.x;
    const float* xp = x + (size_t)c * Ll;
    float s = 0.f, s2 = 0.f;
    for (int i = tid; i < Bb * Ll; i += 256) {
        int b = i >> 10, l = i & (Ll - 1);
        float v = xp[(size_t)b * Cc * Ll + l];
        s += v; s2 += v * v;
    }
    __shared__ float sh1[256], sh2[256];
    sh1[tid] = s; sh2[tid] = s2; __syncthreads();
    for (int o = 128; o > 0; o >>= 1) {
        if (tid < o) { sh1[tid] += sh1[tid + o]; sh2[tid] += sh2[tid + o]; }
        __syncthreads();
    }
    if (tid == 0) {
        const float inv_n = 1.f / (float)(Bb * Ll);
        float mean = sh1[0] * inv_n;
        float var = sh2[0] * inv_n - mean * mean;
        float sc = gamma[c] * rsqrtf(var + BN_EPS);
        g_scale[c] = sc;
        g_shift[c] = beta[c] - mean * sc;
    }
}

// ============================================================
// 2) Fold BN affine into stacked QKV weights/biases
// ============================================================
__global__ __launch_bounds__(256) void fold_kernel(
    const float* __restrict__ Wq, const float* __restrict__ bq,
    const float* __restrict__ Wk, const float* __restrict__ bk,
    const float* __restrict__ Wv, const float* __restrict__ bv)
{
    int o = blockIdx.x;           // 0..1535
    int r = o & (Cc - 1);
    const float* W; const float* bb;
    if (o < Cc)          { W = Wq; bb = bq; }
    else if (o < 2 * Cc) { W = Wk; bb = bk; }
    else                 { W = Wv; bb = bv; }
    int tid = threadIdx.x;
    float acc = 0.f;
    for (int c = tid; c < Cc; c += 256) {
        float w = W[r * Cc + c];
        g_Wall[o * Cc + c] = w * g_scale[c];
        acc += w * g_shift[c];
    }
    __shared__ float sh[256];
    sh[tid] = acc; __syncthreads();
    for (int off = 128; off > 0; off >>= 1) {
        if (tid < off) sh[tid] += sh[tid + off];
        __syncthreads();
    }
    if (tid == 0) g_ball[o] = bb[r] + sh[0];
}

// ============================================================
// Generic tensor-core GEMM:  C[m][n] = op( sum_k A(k,m) * B(k,n) )
// A_KC: A stored gmem [M][K] (k contiguous)  -> smem As[m][36]
//  else A stored gmem [K][M] (m contiguous)  -> smem As[k][136]
// B_KC: B stored gmem [N][K] (k contiguous)  -> smem Bs[n][36]
//  else B stored gmem [K][N] (n contiguous)  -> smem Bs[k][136]
// Tile: 128x128x32, 8 warps (2x4), warp tile 64x32, mma.sync m16n8k8 tf32.
// EPI: 0 = plain, 1 = +bias[row], 2 = *scale, 3 = +bias[row]+resid
// ============================================================
template<bool A_KC, bool B_KC, int EPI>
__global__ __launch_bounds__(256) void gemm_tc(
    const float* __restrict__ Ag, const float* __restrict__ Bg,
    float* __restrict__ Cg, int Kdim, int ldA, int ldB, int ldC,
    size_t sA, size_t sB, size_t sC,
    const float* __restrict__ bias, const float* __restrict__ resid,
    float scale)
{
    constexpr int ASZ = A_KC ? 128 * 36 : 32 * 136;
    constexpr int BSZ = B_KC ? 128 * 36 : 32 * 136;
    extern __shared__ float sm[];
    float* AsBuf[2] = { sm, sm + ASZ };
    float* BsBuf[2] = { sm + 2 * ASZ, sm + 2 * ASZ + BSZ };

    const int tid = threadIdx.x;
    const int lane = tid & 31, wid = tid >> 5;
    const int lr = lane >> 2, lc = lane & 3;
    const int wm = (wid >> 2) * 64;          // warp m origin (0/64)
    const int wn = (wid & 3) * 32;           // warp n origin (0/32/64/96)
    const int m0 = blockIdx.y * 128, n0 = blockIdx.x * 128;
    const int bz = blockIdx.z;

    const float* Ap = Ag + sA * bz;
    const float* Bp = Bg + sB * bz;
    float* Cp = Cg + sC * bz;

    // ---- loader addressing ----
    const float* aptr; int aSm, aSmPass; size_t aGPass, aGStage;
    if (A_KC) {
        int r = tid >> 3, c4 = (tid & 7) * 4;
        aptr = Ap + (size_t)(m0 + r) * ldA + c4;
        aSm = r * 36 + c4; aSmPass = 32 * 36;
        aGPass = (size_t)32 * ldA; aGStage = 32;
    } else {
        int r = tid >> 5, c4 = (tid & 31) * 4;
        aptr = Ap + (size_t)r * ldA + m0 + c4;
        aSm = r * 136 + c4; aSmPass = 8 * 136;
        aGPass = (size_t)8 * ldA; aGStage = (size_t)32 * ldA;
    }
    const float* bptr; int bSm, bSmPass; size_t bGPass, bGStage;
    if (B_KC) {
        int r = tid >> 3, c4 = (tid & 7) * 4;
        bptr = Bp + (size_t)(n0 + r) * ldB + c4;
        bSm = r * 36 + c4; bSmPass = 32 * 36;
        bGPass = (size_t)32 * ldB; bGStage = 32;
    } else {
        int r = tid >> 5, c4 = (tid & 31) * 4;
        bptr = Bp + (size_t)r * ldB + n0 + c4;
        bSm = r * 136 + c4; bSmPass = 8 * 136;
        bGPass = (size_t)8 * ldB; bGStage = (size_t)32 * ldB;
    }

    float acc[4][4][4];
#pragma unroll
    for (int i = 0; i < 4; i++)
#pragma unroll
        for (int j = 0; j < 4; j++)
#pragma unroll
            for (int q = 0; q < 4; q++) acc[i][j][q] = 0.f;

    float4 ra[4], rb[4];
    const int nStages = Kdim / 32;

    // prologue: stage 0
#pragma unroll
    for (int i = 0; i < 4; i++) {
        ra[i] = *(const float4*)(aptr + i * aGPass);
        rb[i] = *(const float4*)(bptr + i * bGPass);
    }
    {
        float* As = AsBuf[0]; float* Bs = BsBuf[0];
#pragma unroll
        for (int i = 0; i < 4; i++) {
            int ia = aSm + i * aSmPass;
            As[ia] = to_tf32(ra[i].x); As[ia + 1] = to_tf32(ra[i].y);
            As[ia + 2] = to_tf32(ra[i].z); As[ia + 3] = to_tf32(ra[i].w);
            int ib = bSm + i * bSmPass;
            Bs[ib] = to_tf32(rb[i].x); Bs[ib + 1] = to_tf32(rb[i].y);
            Bs[ib + 2] = to_tf32(rb[i].z); Bs[ib + 3] = to_tf32(rb[i].w);
        }
    }
    __syncthreads();

    for (int s = 0; s < nStages; s++) {
        int cur = s & 1, nxt = cur ^ 1;
        if (s + 1 < nStages) {
            const float* ap = aptr + (size_t)(s + 1) * aGStage;
            const float* bp2 = bptr + (size_t)(s + 1) * bGStage;
#pragma unroll
            for (int i = 0; i < 4; i++) {
                ra[i] = *(const float4*)(ap + i * aGPass);
                rb[i] = *(const float4*)(bp2 + i * bGPass);
            }
        }
        // ---- compute current stage ----
        const uint32_t* Au = (const uint32_t*)AsBuf[cur];
        const uint32_t* Bu = (const uint32_t*)BsBuf[cur];
#pragma unroll
        for (int kk4 = 0; kk4 < 4; kk4++) {
            const int kk = kk4 * 8;
            uint32_t af[4][4], bf[4][2];
#pragma unroll
            for (int mt = 0; mt < 4; mt++) {
                if (A_KC) {
                    int base = (wm + mt * 16 + lr) * 36 + kk + lc;
                    af[mt][0] = Au[base];           af[mt][1] = Au[base + 8 * 36];
                    af[mt][2] = Au[base + 4];       af[mt][3] = Au[base + 8 * 36 + 4];
                } else {
                    int base = (kk + lc) * 136 + wm + mt * 16 + lr;
                    af[mt][0] = Au[base];           af[mt][1] = Au[base + 8];
                    af[mt][2] = Au[base + 4 * 136]; af[mt][3] = Au[base + 4 * 136 + 8];
                }
            }
#pragma unroll
            for (int nt = 0; nt < 4; nt++) {
                if (B_KC) {
                    int base = (wn + nt * 8 + lr) * 36 + kk + lc;
                    bf[nt][0] = Bu[base]; bf[nt][1] = Bu[base + 4];
                } else {
                    int base = (kk + lc) * 136 + wn + nt * 8 + lr;
                    bf[nt][0] = Bu[base]; bf[nt][1] = Bu[base + 4 * 136];
                }
            }
#pragma unroll
            for (int mt = 0; mt < 4; mt++)
#pragma unroll
                for (int nt = 0; nt < 4; nt++) {
                    asm volatile(
                        "mma.sync.aligned.m16n8k8.row.col.f32.tf32.tf32.f32 "
                        "{%0,%1,%2,%3}, {%4,%5,%6,%7}, {%8,%9}, {%0,%1,%2,%3};"
                        : "+f"(acc[mt][nt][0]), "+f"(acc[mt][nt][1]),
                          "+f"(acc[mt][nt][2]), "+f"(acc[mt][nt][3])
                        : "r"(af[mt][0]), "r"(af[mt][1]), "r"(af[mt][2]), "r"(af[mt][3]),
                          "r"(bf[nt][0]), "r"(bf[nt][1]));
                }
        }
        // ---- store next stage ----
        if (s + 1 < nStages) {
            float* As = AsBuf[nxt]; float* Bs = BsBuf[nxt];
#pragma unroll
            for (int i = 0; i < 4; i++) {
                int ia = aSm + i * aSmPass;
                As[ia] = to_tf32(ra[i].x); As[ia + 1] = to_tf32(ra[i].y);
                As[ia + 2] = to_tf32(ra[i].z); As[ia + 3] = to_tf32(ra[i].w);
                int ib = bSm + i * bSmPass;
                Bs[ib] = to_tf32(rb[i].x); Bs[ib + 1] = to_tf32(rb[i].y);
                Bs[ib + 2] = to_tf32(rb[i].z); Bs[ib + 3] = to_tf32(rb[i].w);
            }
            __syncthreads();
        }
    }

    // ---- epilogue ----
#pragma unroll
    for (int mt = 0; mt < 4; mt++) {
#pragma unroll
        for (int nt = 0; nt < 4; nt++) {
            int row = m0 + wm + mt * 16 + lr;
            int col = n0 + wn + nt * 8 + 2 * lc;
            float v0 = acc[mt][nt][0], v1 = acc[mt][nt][1];
            float v2 = acc[mt][nt][2], v3 = acc[mt][nt][3];
            if (EPI == 1) {
                float b0 = bias[row], b1 = bias[row + 8];
                v0 += b0; v1 += b0; v2 += b1; v3 += b1;
            } else if (EPI == 2) {
                v0 *= scale; v1 *= scale; v2 *= scale; v3 *= scale;
            } else if (EPI == 3) {
                float b0 = bias[row], b1 = bias[row + 8];
                const float* rp = resid + sC * bz;
                float2 r0 = *(const float2*)&rp[(size_t)row * ldC + col];
                float2 r1 = *(const float2*)&rp[(size_t)(row + 8) * ldC + col];
                v0 += b0 + r0.x; v1 += b0 + r0.y;
                v2 += b1 + r1.x; v3 += b1 + r1.y;
            }
            *(float2*)&Cp[(size_t)row * ldC + col] = make_float2(v0, v1);
            *(float2*)&Cp[(size_t)(row + 8) * ldC + col] = make_float2(v2, v3);
        }
    }
}

// ============================================================
// Row softmax over the last dim of S (in place). One block per row.
// ============================================================
__global__ __launch_bounds__(256) void softmax_kernel()
{
    size_t row = blockIdx.x;   // b*L + i
    float* Sp = g_S + row * (size_t)Ll;
    int tid = threadIdx.x;
    float4 v = ((float4*)Sp)[tid];

    __shared__ float sh[256];
    float mx = fmaxf(fmaxf(v.x, v.y), fmaxf(v.z, v.w));
    sh[tid] = mx; __syncthreads();
    for (int o = 128; o > 0; o >>= 1) {
        if (tid < o) sh[tid] = fmaxf(sh[tid], sh[tid + o]);
        __syncthreads();
    }
    float rowmax = sh[0];
    __syncthreads();

    v.x = __expf(v.x - rowmax); v.y = __expf(v.y - rowmax);
    v.z = __expf(v.z - rowmax); v.w = __expf(v.w - rowmax);
    sh[tid] = v.x + v.y + v.z + v.w; __syncthreads();
    for (int o = 128; o > 0; o >>= 1) {
        if (tid < o) sh[tid] += sh[tid + o];
        __syncthreads();
    }
    float inv = 1.f / sh[0];
    v.x *= inv; v.y *= inv; v.z *= inv; v.w *= inv;
    ((float4*)Sp)[tid] = v;
}

// ============================================================
extern "C" void kernel_launch(void* const* d_in, const int* in_sizes, int n_in,
                              void* d_out, int out_size)
{
    const float* x     = (const float*)d_in[0];
    const float* gamma = (const float*)d_in[1];
    const float* beta  = (const float*)d_in[2];
    const float* Wq    = (const float*)d_in[3];
    const float* bq    = (const float*)d_in[4];
    const float* Wk    = (const float*)d_in[5];
    const float* bk    = (const float*)d_in[6];
    const float* Wv    = (const float*)d_in[7];
    const float* bv    = (const float*)d_in[8];
    const float* Wp    = (const float*)d_in[9];
    const float* bp    = (const float*)d_in[10];
    float* out = (float*)d_out;

    float* qkv; cudaGetSymbolAddress((void**)&qkv, g_qkv);
    float* Sbuf; cudaGetSymbolAddress((void**)&Sbuf, g_S);
    float* hbuf; cudaGetSymbolAddress((void**)&hbuf, g_h);
    float* Wall; cudaGetSymbolAddress((void**)&Wall, g_Wall);
    float* ball; cudaGetSymbolAddress((void**)&ball, g_ball);

    const int SM_TF = (128 * 36 + 32 * 136) * 2 * 4;   // A_KC, !B_KC : 71680
    const int SM_FF = (32 * 136 + 32 * 136) * 2 * 4;   // !A_KC, !B_KC: 69632
    const int SM_TT = (128 * 36 + 128 * 36) * 2 * 4;   // A_KC, B_KC : 73728

    cudaFuncSetAttribute(gemm_tc<true,  false, 1>, cudaFuncAttributeMaxDynamicSharedMemorySize, SM_TF);
    cudaFuncSetAttribute(gemm_tc<false, false, 2>, cudaFuncAttributeMaxDynamicSharedMemorySize, SM_FF);
    cudaFuncSetAttribute(gemm_tc<true,  true,  0>, cudaFuncAttributeMaxDynamicSharedMemorySize, SM_TT);
    cudaFuncSetAttribute(gemm_tc<true,  false, 3>, cudaFuncAttributeMaxDynamicSharedMemorySize, SM_TF);

    bn_stats_kernel<<<Cc, 256>>>(x, gamma, beta);
    fold_kernel<<<C3, 256>>>(Wq, bq, Wk, bk, Wv, bv);

    // QKV: qkv[o][l] = sum_c Wall[o][c] x[c][l] + ball[o]
    gemm_tc<true, false, 1><<<dim3(Ll / 128, C3 / 128, Bb), 256, SM_TF>>>(
        Wall, x, qkv, Cc, Cc, Ll, Ll,
        0, (size_t)Cc * Ll, (size_t)C3 * Ll, ball, nullptr, 0.f);

    // scores: S[i][j] = (1/sqrt(C)) sum_c q[c][i] k[c][j]
    gemm_tc<false, false, 2><<<dim3(Ll / 128, Ll / 128, Bb), 256, SM_FF>>>(
        qkv, qkv + (size_t)Cc * Ll, Sbuf, Cc, Ll, Ll, Ll,
        (size_t)C3 * Ll, (size_t)C3 * Ll, (size_t)Ll * Ll,
        nullptr, nullptr, rsqrtf((float)Cc));

    softmax_kernel<<<Bb * Ll, 256>>>();

    // AV: h[c][i] = sum_j V[c][j] P[i][j]
    gemm_tc<true, true, 0><<<dim3(Ll / 128, Cc / 128, Bb), 256, SM_TT>>>(
        qkv + (size_t)2 * Cc * Ll, Sbuf, hbuf, Ll, Ll, Ll, Ll,
        (size_t)C3 * Ll, (size_t)Ll * Ll, (size_t)Cc * Ll,
        nullptr, nullptr, 0.f);

    // proj: out[o][l] = x[o][l] + bp[o] + sum_c Wp[o][c] h[c][l]
    gemm_tc<true, false, 3><<<dim3(Ll / 128, Cc / 128, Bb), 256, SM_TF>>>(
        Wp, hbuf, out, Cc, Cc, Ll, Ll,
        0, (size_t)Cc * Ll, (size_t)Cc * Ll, bp, x, 0.f);
}

// round 3
// speedup vs baseline: 5.0136x; 2.0283x over previous
#include <cuda_runtime.h>
#include <cuda_bf16.h>
#include <math.h>
#include <stdint.h>

#define Bb 16
#define Cc 512
#define Ll 1024
#define C3 1536
#define BN_EPS 1e-5f

// ---- scratch (no allocations allowed) ----
__device__ float g_scale[Cc];
__device__ float g_shift[Cc];
__device__ float g_ball[C3];
__device__ __nv_bfloat16 g_Wall[C3 * Cc];                 // folded QKV weights bf16
__device__ __nv_bfloat16 g_Wpb[Cc * Cc];                  // Wp bf16
__device__ __nv_bfloat16 g_xb[(size_t)Bb * Cc * Ll];      // x bf16
__device__ __nv_bfloat16 g_qkv[(size_t)Bb * C3 * Ll];     // qkv bf16
__device__ float g_S[(size_t)Bb * Ll * Ll];               // scores fp32
__device__ __nv_bfloat16 g_P[(size_t)Bb * Ll * Ll];       // probs bf16
__device__ __nv_bfloat16 g_h[(size_t)Bb * Cc * Ll];       // attn out bf16

// ---------------- PTX helpers ----------------
__device__ __forceinline__ void cp16(uint32_t saddr, const void* gaddr) {
    asm volatile("cp.async.cg.shared.global [%0], [%1], 16;\n" :: "r"(saddr), "l"(gaddr));
}
__device__ __forceinline__ void cp_commit() { asm volatile("cp.async.commit_group;\n"); }
__device__ __forceinline__ void ldsm_x4(uint32_t* r, uint32_t a) {
    asm volatile("ldmatrix.sync.aligned.m8n8.x4.shared.b16 {%0,%1,%2,%3}, [%4];"
                 : "=r"(r[0]), "=r"(r[1]), "=r"(r[2]), "=r"(r[3]) : "r"(a));
}
__device__ __forceinline__ void ldsm_x4t(uint32_t* r, uint32_t a) {
    asm volatile("ldmatrix.sync.aligned.m8n8.x4.trans.shared.b16 {%0,%1,%2,%3}, [%4];"
                 : "=r"(r[0]), "=r"(r[1]), "=r"(r[2]), "=r"(r[3]) : "r"(a));
}
__device__ __forceinline__ void ldsm_x2(uint32_t* r, uint32_t a) {
    asm volatile("ldmatrix.sync.aligned.m8n8.x2.shared.b16 {%0,%1}, [%2];"
                 : "=r"(r[0]), "=r"(r[1]) : "r"(a));
}
__device__ __forceinline__ void ldsm_x2t(uint32_t* r, uint32_t a) {
    asm volatile("ldmatrix.sync.aligned.m8n8.x2.trans.shared.b16 {%0,%1}, [%2];"
                 : "=r"(r[0]), "=r"(r[1]) : "r"(a));
}
__device__ __forceinline__ void mma_bf16(float* c, const uint32_t* a, const uint32_t* b) {
    asm volatile(
        "mma.sync.aligned.m16n8k16.row.col.f32.bf16.bf16.f32 "
        "{%0,%1,%2,%3}, {%4,%5,%6,%7}, {%8,%9}, {%0,%1,%2,%3};"
        : "+f"(c[0]), "+f"(c[1]), "+f"(c[2]), "+f"(c[3])
        : "r"(a[0]), "r"(a[1]), "r"(a[2]), "r"(a[3]), "r"(b[0]), "r"(b[1]));
}

// ============================================================
// BatchNorm batch statistics -> per-channel scale/shift
// ============================================================
__global__ __launch_bounds__(256) void bn_stats_kernel(
    const float* __restrict__ x, const float* __restrict__ gamma,
    const float* __restrict__ beta)
{
    int c = blockIdx.x;
    int tid = threadIdx.x;
    const float* xp = x + (size_t)c * Ll;
    float s = 0.f, s2 = 0.f;
    for (int i = tid; i < Bb * Ll; i += 256) {
        int b = i >> 10, l = i & (Ll - 1);
        float v = xp[(size_t)b * Cc * Ll + l];
        s += v; s2 += v * v;
    }
    __shared__ float sh1[256], sh2[256];
    sh1[tid] = s; sh2[tid] = s2; __syncthreads();
    for (int o = 128; o > 0; o >>= 1) {
        if (tid < o) { sh1[tid] += sh1[tid + o]; sh2[tid] += sh2[tid + o]; }
        __syncthreads();
    }
    if (tid == 0) {
        const float inv_n = 1.f / (float)(Bb * Ll);
        float mean = sh1[0] * inv_n;
        float var = s2 = sh2[0] * inv_n - mean * mean;
        float sc = gamma[c] * rsqrtf(var + BN_EPS);
        g_scale[c] = sc;
        g_shift[c] = beta[c] - mean * sc;
    }
}

// ============================================================
// Fold BN into stacked QKV weights (bf16 out) + biases
// ============================================================
__global__ __launch_bounds__(256) void fold_kernel(
    const float* __restrict__ Wq, const float* __restrict__ bq,
    const float* __restrict__ Wk, const float* __restrict__ bk,
    const float* __restrict__ Wv, const float* __restrict__ bv)
{
    int o = blockIdx.x;
    int r = o & (Cc - 1);
    const float* W; const float* bb;
    if (o < Cc)          { W = Wq; bb = bq; }
    else if (o < 2 * Cc) { W = Wk; bb = bk; }
    else                 { W = Wv; bb = bv; }
    int tid = threadIdx.x;
    float acc = 0.f;
    for (int c = tid; c < Cc; c += 256) {
        float w = W[r * Cc + c];
        g_Wall[o * Cc + c] = __float2bfloat16(w * g_scale[c]);
        acc += w * g_shift[c];
    }
    __shared__ float sh[256];
    sh[tid] = acc; __syncthreads();
    for (int off = 128; off > 0; off >>= 1) {
        if (tid < off) sh[tid] += sh[tid + off];
        __syncthreads();
    }
    if (tid == 0) g_ball[o] = bb[r] + sh[0];
}

// ============================================================
// fp32 -> bf16 conversion (4 elements / thread)
// ============================================================
__global__ __launch_bounds__(256) void conv_kernel(
    const float* __restrict__ in, __nv_bfloat16* __restrict__ outp)
{
    size_t i = ((size_t)blockIdx.x * 256 + threadIdx.x) * 4;
    float4 v = *(const float4*)(in + i);
    __nv_bfloat162 h0 = { __float2bfloat16(v.x), __float2bfloat16(v.y) };
    __nv_bfloat162 h1 = { __float2bfloat16(v.z), __float2bfloat16(v.w) };
    *(__nv_bfloat162*)(outp + i) = h0;
    *(__nv_bfloat162*)(outp + i + 2) = h1;
}

// ============================================================
// bf16 tensor-core GEMM: C[m][n] = op( sum_k A(k,m)*B(k,n) )
// A_KC: A gmem [M][K] k-contig -> smem [m][40]; else [K][M] -> smem [k][136]
// B_KC analogous with N.  Tile 128x128x32, 8 warps (64x32 each),
// mma m16n8k16 bf16, cp.async double buffer, ldmatrix fragments.
// EPI: 0 plain->bf16, 1 +bias->bf16, 2 *scale->f32, 3 +bias+resid->f32
// ============================================================
template<bool A_KC, bool B_KC, int EPI>
__global__ __launch_bounds__(256) void gemm_bf(
    const __nv_bfloat16* __restrict__ Ag, const __nv_bfloat16* __restrict__ Bg,
    void* __restrict__ Cg, int Kdim, int ldA, int ldB, int ldC,
    size_t sA, size_t sB, size_t sC,
    const float* __restrict__ bias, const float* __restrict__ resid,
    float scale)
{
    constexpr int ABYTES = A_KC ? 128 * 40 * 2 : 32 * 136 * 2;
    constexpr int BBYTES = B_KC ? 128 * 40 * 2 : 32 * 136 * 2;
    __shared__ __align__(16) unsigned char smem_raw[2 * (ABYTES + BBYTES)];
    const uint32_t smem0 = (uint32_t)__cvta_generic_to_shared(smem_raw);
    const uint32_t aBuf[2] = { smem0, smem0 + ABYTES };
    const uint32_t bBuf[2] = { smem0 + 2 * ABYTES, smem0 + 2 * ABYTES + BBYTES };

    const int tid = threadIdx.x;
    const int lane = tid & 31, wid = tid >> 5;
    const int lr = lane >> 2, lc = lane & 3;
    const int wm = (wid >> 2) * 64;
    const int wn = (wid & 3) * 32;
    const int m0 = blockIdx.y * 128, n0 = blockIdx.x * 128;
    const int bz = blockIdx.z;

    const __nv_bfloat16* Ap = Ag + sA * bz;
    const __nv_bfloat16* Bp = Bg + sB * bz;

    // ---- cp.async loader setup (2x 16B chunks per thread per operand) ----
    const __nv_bfloat16* ag; uint32_t aSm; size_t aStep;
    if (A_KC) {
        int r = tid >> 1, c = (tid & 1) * 2;
        ag = Ap + (size_t)(m0 + r) * ldA + c * 8;
        aSm = r * 80 + c * 16; aStep = 32;
    } else {
        int r = tid >> 3, c = (tid & 7) * 2;
        ag = Ap + (size_t)r * ldA + m0 + c * 8;
        aSm = r * 272 + c * 16; aStep = (size_t)32 * ldA;
    }
    const __nv_bfloat16* bg; uint32_t bSm; size_t bStep;
    if (B_KC) {
        int r = tid >> 1, c = (tid & 1) * 2;
        bg = Bp + (size_t)(n0 + r) * ldB + c * 8;
        bSm = r * 80 + c * 16; bStep = 32;
    } else {
        int r = tid >> 3, c = (tid & 7) * 2;
        bg = Bp + (size_t)r * ldB + n0 + c * 8;
        bSm = r * 272 + c * 16; bStep = (size_t)32 * ldB;
    }

    // ---- ldmatrix fragment base offsets (bytes) ----
    uint32_t abase, bbase;
    if (A_KC)
        abase = (uint32_t)((wm + (lane & 15)) * 40 + (lane >> 4) * 8) * 2;
    else
        abase = (uint32_t)((((lane & 7) + ((lane >> 4) << 3)) * 136) + wm + ((lane >> 3) & 1) * 8) * 2;
    if (B_KC)
        bbase = (uint32_t)((wn + (lane & 7)) * 40 + ((lane >> 3) & 1) * 8) * 2;
    else
        bbase = (uint32_t)(((lane & 15)) * 136 + wn) * 2;

    float acc[4][4][4];
#pragma unroll
    for (int i = 0; i < 4; i++)
#pragma unroll
        for (int j = 0; j < 4; j++)
#pragma unroll
            for (int q = 0; q < 4; q++) acc[i][j][q] = 0.f;

    const int nStages = Kdim / 32;

    // prologue
    {
        cp16(aBuf[0] + aSm, ag);          cp16(aBuf[0] + aSm + 16, ag + 8);
        cp16(bBuf[0] + bSm, bg);          cp16(bBuf[0] + bSm + 16, bg + 8);
        cp_commit();
    }

    for (int s = 0; s < nStages; s++) {
        const int cur = s & 1;
        if (s + 1 < nStages) {
            const int nxt = cur ^ 1;
            const __nv_bfloat16* an = ag + (size_t)(s + 1) * aStep;
            const __nv_bfloat16* bn = bg + (size_t)(s + 1) * bStep;
            cp16(aBuf[nxt] + aSm, an);    cp16(aBuf[nxt] + aSm + 16, an + 8);
            cp16(bBuf[nxt] + bSm, bn);    cp16(bBuf[nxt] + bSm + 16, bn + 8);
            cp_commit();
            asm volatile("cp.async.wait_group 1;\n");
        } else {
            asm volatile("cp.async.wait_group 0;\n");
        }
        __syncthreads();

        const uint32_t aB = aBuf[cur], bB = bBuf[cur];
#pragma unroll
        for (int ks = 0; ks < 2; ks++) {
            uint32_t af[4][4], bf[4][2];
#pragma unroll
            for (int mt = 0; mt < 4; mt++) {
                uint32_t addr = aB + abase +
                    (A_KC ? (mt * 16 * 40 + ks * 16) * 2 : (mt * 16 + ks * 16 * 136) * 2);
                if (A_KC) ldsm_x4(af[mt], addr); else ldsm_x4t(af[mt], addr);
            }
#pragma unroll
            for (int nt = 0; nt < 4; nt++) {
                uint32_t addr = bB + bbase +
                    (B_KC ? (nt * 8 * 40 + ks * 16) * 2 : (nt * 8 + ks * 16 * 136) * 2);
                if (B_KC) ldsm_x2(bf[nt], addr); else ldsm_x2t(bf[nt], addr);
            }
#pragma unroll
            for (int mt = 0; mt < 4; mt++)
#pragma unroll
                for (int nt = 0; nt < 4; nt++)
                    mma_bf16(acc[mt][nt], af[mt], bf[nt]);
        }
        __syncthreads();
    }

    // ---- epilogue ----
#pragma unroll
    for (int mt = 0; mt < 4; mt++) {
#pragma unroll
        for (int nt = 0; nt < 4; nt++) {
            int row = m0 + wm + mt * 16 + lr;
            int col = n0 + wn + nt * 8 + 2 * lc;
            float v0 = acc[mt][nt][0], v1 = acc[mt][nt][1];
            float v2 = acc[mt][nt][2], v3 = acc[mt][nt][3];
            if (EPI == 1) {
                float b0 = bias[row], b1 = bias[row + 8];
                v0 += b0; v1 += b0; v2 += b1; v3 += b1;
            }
            if (EPI == 0 || EPI == 1) {
                __nv_bfloat16* Cb = (__nv_bfloat16*)Cg + sC * bz;
                __nv_bfloat162 p0 = { __float2bfloat16(v0), __float2bfloat16(v1) };
                __nv_bfloat162 p1 = { __float2bfloat16(v2), __float2bfloat16(v3) };
                *(__nv_bfloat162*)&Cb[(size_t)row * ldC + col] = p0;
                *(__nv_bfloat162*)&Cb[(size_t)(row + 8) * ldC + col] = p1;
            } else {
                float* Cf = (float*)Cg + sC * bz;
                if (EPI == 2) {
                    v0 *= scale; v1 *= scale; v2 *= scale; v3 *= scale;
                } else {
                    float b0 = bias[row], b1 = bias[row + 8];
                    const float* rp = resid + sC * bz;
                    float2 r0 = *(const float2*)&rp[(size_t)row * ldC + col];
                    float2 r1 = *(const float2*)&rp[(size_t)(row + 8) * ldC + col];
                    v0 += b0 + r0.x; v1 += b0 + r0.y;
                    v2 += b1 + r1.x; v3 += b1 + r1.y;
                }
                *(float2*)&Cf[(size_t)row * ldC + col] = make_float2(v0, v1);
                *(float2*)&Cf[(size_t)(row + 8) * ldC + col] = make_float2(v2, v3);
            }
        }
    }
}

// ============================================================
// Row softmax: S fp32 -> P bf16
// ============================================================
__global__ __launch_bounds__(256) void softmax_kernel()
{
    size_t row = blockIdx.x;
    const float* Sp = g_S + row * (size_t)Ll;
    __nv_bfloat16* Pp = g_P + row * (size_t)Ll;
    int tid = threadIdx.x;
    float4 v = ((const float4*)Sp)[tid];

    __shared__ float sh[256];
    float mx = fmaxf(fmaxf(v.x, v.y), fmaxf(v.z, v.w));
    sh[tid] = mx; __syncthreads();
    for (int o = 128; o > 0; o >>= 1) {
        if (tid < o) sh[tid] = fmaxf(sh[tid], sh[tid + o]);
        __syncthreads();
    }
    float rowmax = sh[0];
    __syncthreads();

    v.x = __expf(v.x - rowmax); v.y = __expf(v.y - rowmax);
    v.z = __expf(v.z - rowmax); v.w = __expf(v.w - rowmax);
    sh[tid] = v.x + v.y + v.z + v.w; __syncthreads();
    for (int o = 128; o > 0; o >>= 1) {
        if (tid < o) sh[tid] += sh[tid + o];
        __syncthreads();
    }
    float inv = 1.f / sh[0];
    __nv_bfloat162 p0 = { __float2bfloat16(v.x * inv), __float2bfloat16(v.y * inv) };
    __nv_bfloat162 p1 = { __float2bfloat16(v.z * inv), __float2bfloat16(v.w * inv) };
    *(__nv_bfloat162*)&Pp[tid * 4] = p0;
    *(__nv_bfloat162*)&Pp[tid * 4 + 2] = p1;
}

// ============================================================
extern "C" void kernel_launch(void* const* d_in, const int* in_sizes, int n_in,
                              void* d_out, int out_size)
{
    const float* x     = (const float*)d_in[0];
    const float* gamma = (const float*)d_in[1];
    const float* beta  = (const float*)d_in[2];
    const float* Wq    = (const float*)d_in[3];
    const float* bq    = (const float*)d_in[4];
    const float* Wk    = (const float*)d_in[5];
    const float* bk    = (const float*)d_in[6];
    const float* Wv    = (const float*)d_in[7];
    const float* bv    = (const float*)d_in[8];
    const float* Wp    = (const float*)d_in[9];
    const float* bp    = (const float*)d_in[10];
    float* out = (float*)d_out;

    __nv_bfloat16 *Wall, *Wpb, *xb, *qkv, *P, *h;
    float *S, *ball;
    cudaGetSymbolAddress((void**)&Wall, g_Wall);
    cudaGetSymbolAddress((void**)&Wpb,  g_Wpb);
    cudaGetSymbolAddress((void**)&xb,   g_xb);
    cudaGetSymbolAddress((void**)&qkv,  g_qkv);
    cudaGetSymbolAddress((void**)&P,    g_P);
    cudaGetSymbolAddress((void**)&h,    g_h);
    cudaGetSymbolAddress((void**)&S,    g_S);
    cudaGetSymbolAddress((void**)&ball, g_ball);

    bn_stats_kernel<<<Cc, 256>>>(x, gamma, beta);
    fold_kernel<<<C3, 256>>>(Wq, bq, Wk, bk, Wv, bv);
    conv_kernel<<<(Bb * Cc * Ll) / 1024, 256>>>(x, xb);
    conv_kernel<<<(Cc * Cc) / 1024, 256>>>(Wp, Wpb);

    // QKV: qkv[o][l] = sum_c Wall[o][c] xb[c][l] + ball[o]   -> bf16
    gemm_bf<true, false, 1><<<dim3(Ll / 128, C3 / 128, Bb), 256>>>(
        Wall, xb, qkv, Cc, Cc, Ll, Ll,
        0, (size_t)Cc * Ll, (size_t)C3 * Ll, ball, nullptr, 0.f);

    // scores: S[i][j] = (1/sqrt(C)) sum_c q[c][i] k[c][j]    -> fp32
    gemm_bf<false, false, 2><<<dim3(Ll / 128, Ll / 128, Bb), 256>>>(
        qkv, qkv + (size_t)Cc * Ll, S, Cc, Ll, Ll, Ll,
        (size_t)C3 * Ll, (size_t)C3 * Ll, (size_t)Ll * Ll,
        nullptr, nullptr, rsqrtf((float)Cc));

    softmax_kernel<<<Bb * Ll, 256>>>();

    // AV: h[c][i] = sum_j V[c][j] P[i][j]                    -> bf16
    gemm_bf<true, true, 0><<<dim3(Ll / 128, Cc / 128, Bb), 256>>>(
        qkv + (size_t)2 * Cc * Ll, P, h, Ll, Ll, Ll, Ll,
        (size_t)C3 * Ll, (size_t)Ll * Ll, (size_t)Cc * Ll,
        nullptr, nullptr, 0.f);

    // proj: out[o][l] = x[o][l] + bp[o] + sum_c Wp[o][c] h[c][l]  -> fp32
    gemm_bf<true, false, 3><<<dim3(Ll / 128, Cc / 128, Bb), 256>>>(
        Wpb, h, out, Cc, Cc, Ll, Ll,
        0, (size_t)Cc * Ll, (size_t)Cc * Ll, bp, x, 0.f);
}